// round 4
// baseline (speedup 1.0000x reference)
#include <cuda_runtime.h>
#include <cstdint>

// Problem constants
#define T_TOK 8192
#define DIM   1024
#define NEXP  16
#define TOPK  2
#define INTER 2048
#define NA    (T_TOK * TOPK)        // 16384 assignments
#define NAP   18432                 // NA + 16*128 padding capacity
#define NT_MAX 144                  // max 128-row M tiles (128 + 16 pad tiles)

// ---------------- static device scratch (no allocations allowed) -------------
__device__ int   g_counts[NEXP];
__device__ int   g_poff[NEXP];
__device__ int   g_cursor[NEXP];
__device__ int   g_tile_e[NT_MAX];
__device__ int   g_tok_e[NA];
__device__ float g_tok_w[NA];
__device__ int   g_tok_slot[NA];
__device__ float g_Xg[(size_t)NAP * DIM];    // gathered tokens, expert-contiguous
__device__ float g_H [(size_t)NAP * INTER];  // GLU hidden
__device__ float g_O [(size_t)NAP * DIM];    // per-assignment expert output

// ---------------- helpers ----------------------------------------------------
__device__ __forceinline__ uint32_t f2tf32(float f) {
    uint32_t r;
    asm("cvt.rna.tf32.f32 %0, %1;\n" : "=r"(r) : "f"(f));
    return r;
}

__device__ __forceinline__ void mma_tf32(float* d, const uint32_t* a,
                                         uint32_t b0, uint32_t b1) {
    asm volatile(
        "mma.sync.aligned.m16n8k8.row.col.f32.tf32.tf32.f32 "
        "{%0,%1,%2,%3},{%4,%5,%6,%7},{%8,%9},{%0,%1,%2,%3};\n"
        : "+f"(d[0]), "+f"(d[1]), "+f"(d[2]), "+f"(d[3])
        : "r"(a[0]), "r"(a[1]), "r"(a[2]), "r"(a[3]), "r"(b0), "r"(b1));
}

__device__ __forceinline__ float silu_f(float x) {
    return x / (1.0f + __expf(-x));
}

// ---------------- kernel 0: zero per-launch state ----------------------------
__global__ void zero_kernel() {
    int i = threadIdx.x;
    if (i < NEXP) g_counts[i] = 0;
}

// ---------------- kernel 1: gate (one warp per token) ------------------------
__global__ void gate_kernel(const float* __restrict__ x,
                            const float* __restrict__ Wg,
                            const float* __restrict__ bg) {
    int warp = (blockIdx.x * blockDim.x + threadIdx.x) >> 5;
    int lane = threadIdx.x & 31;
    if (warp >= T_TOK) return;
    const float* xr = x + (size_t)warp * DIM;

    float acc[NEXP];
#pragma unroll
    for (int e = 0; e < NEXP; e++) acc[e] = 0.0f;

    for (int d = lane; d < DIM; d += 32) {
        float xv = __ldg(xr + d);
        const float4* w4 = reinterpret_cast<const float4*>(Wg + (size_t)d * NEXP);
        float4 w0 = w4[0], w1 = w4[1], w2 = w4[2], w3 = w4[3];
        acc[0]  += xv * w0.x; acc[1]  += xv * w0.y; acc[2]  += xv * w0.z; acc[3]  += xv * w0.w;
        acc[4]  += xv * w1.x; acc[5]  += xv * w1.y; acc[6]  += xv * w1.z; acc[7]  += xv * w1.w;
        acc[8]  += xv * w2.x; acc[9]  += xv * w2.y; acc[10] += xv * w2.z; acc[11] += xv * w2.w;
        acc[12] += xv * w3.x; acc[13] += xv * w3.y; acc[14] += xv * w3.z; acc[15] += xv * w3.w;
    }
#pragma unroll
    for (int e = 0; e < NEXP; e++) {
        float v = acc[e];
#pragma unroll
        for (int o = 16; o > 0; o >>= 1) v += __shfl_xor_sync(0xffffffffu, v, o);
        acc[e] = v;
    }
    if (lane == 0) {
        float l1 = -1e30f, l2 = -1e30f;
        int i1 = 0, i2 = 0;
#pragma unroll
        for (int e = 0; e < NEXP; e++) {
            float v = acc[e] + bg[e];
            if (v > l1) { l1 = v; i1 = e; }
        }
#pragma unroll
        for (int e = 0; e < NEXP; e++) {
            float v = acc[e] + bg[e];
            if (e != i1 && v > l2) { l2 = v; i2 = e; }
        }
        // renormalized top-2 softmax weights (global softmax denom cancels)
        float e2 = __expf(l2 - l1);
        float w1v = 1.0f / (1.0f + e2);
        float w2v = e2 * w1v;
        g_tok_e[2 * warp]     = i1;
        g_tok_e[2 * warp + 1] = i2;
        g_tok_w[2 * warp]     = w1v;
        g_tok_w[2 * warp + 1] = w2v;
        atomicAdd(&g_counts[i1], 1);
        atomicAdd(&g_counts[i2], 1);
    }
}

// ---------------- kernel 2: padded offsets + tile->expert map ----------------
__global__ void offsets_kernel() {
    if (threadIdx.x != 0 || blockIdx.x != 0) return;
    int run = 0, idx = 0;
    for (int e = 0; e < NEXP; e++) {
        g_poff[e]   = run;
        g_cursor[e] = 0;
        int c  = g_counts[e];
        int pt = (c + 127) >> 7;                 // padded tile count
        for (int i = 0; i < pt; i++) g_tile_e[idx++] = e;
        run += pt << 7;
    }
    for (; idx < NT_MAX; idx++) g_tile_e[idx] = -1;
}

// ---------------- kernel 3: assign slots + gather rows (warp/assignment) -----
__global__ void assign_gather_kernel(const float* __restrict__ x) {
    int aw   = (blockIdx.x * blockDim.x + threadIdx.x) >> 5;  // assignment id
    int lane = threadIdx.x & 31;
    if (aw >= NA) return;
    int t = aw >> 1;

    int slot = 0;
    if (lane == 0) {
        int e   = g_tok_e[aw];
        int pos = atomicAdd(&g_cursor[e], 1);
        slot    = g_poff[e] + pos;
        g_tok_slot[aw] = slot;
    }
    slot = __shfl_sync(0xffffffffu, slot, 0);

    const float4* src = reinterpret_cast<const float4*>(x + (size_t)t * DIM);
    float4*       dst = reinterpret_cast<float4*>(g_Xg + (size_t)slot * DIM);
#pragma unroll
    for (int i = 0; i < 8; i++) dst[lane + 32 * i] = src[lane + 32 * i];
}

// ---------------- GEMM tiles -------------------------------------------------
#define BM  128
#define BN  64
#define BK  32
#define BKP 36   // A smem pad: frag banks = 4g+tg  -> conflict-free
#define BNP 72   // B smem pad: frag banks = 8tg+g  -> conflict-free

// GEMM1 fused: H = silu(Xg@W1 + b1) * (Xg@W3 + b3)   [rows x 2048]
__global__ __launch_bounds__(256) void gemm1_kernel(
    const float* __restrict__ W1, const float* __restrict__ b1,
    const float* __restrict__ W3, const float* __restrict__ b3) {
    int e = g_tile_e[blockIdx.y];
    if (e < 0) return;
    int m0 = blockIdx.y * BM;
    int n0 = blockIdx.x * BN;

    const float* A  = g_Xg + (size_t)m0 * DIM;
    const float* B1 = W1 + (size_t)e * DIM * INTER + n0;
    const float* B3 = W3 + (size_t)e * DIM * INTER + n0;

    __shared__ float As [BM][BKP];
    __shared__ float Bs1[BK][BNP];
    __shared__ float Bs3[BK][BNP];

    int tid  = threadIdx.x;
    int lane = tid & 31, warp = tid >> 5;
    int wm = (warp >> 1) * 32, wn = (warp & 1) * 32;
    int g  = lane >> 2, tg = lane & 3;

    float acc1[2][4][4] = {};
    float acc3[2][4][4] = {};

    for (int k0 = 0; k0 < DIM; k0 += BK) {
#pragma unroll
        for (int i = 0; i < 4; i++) {                    // A: 1024 float4
            int idx = tid + i * 256;
            int r = idx >> 3, c = (idx & 7) * 4;
            float4 v = *reinterpret_cast<const float4*>(A + (size_t)r * DIM + k0 + c);
            v.x = __uint_as_float(f2tf32(v.x)); v.y = __uint_as_float(f2tf32(v.y));
            v.z = __uint_as_float(f2tf32(v.z)); v.w = __uint_as_float(f2tf32(v.w));
            *reinterpret_cast<float4*>(&As[r][c]) = v;
        }
#pragma unroll
        for (int i = 0; i < 2; i++) {                    // B1/B3: 512 float4 each
            int idx = tid + i * 256;
            int r = idx >> 4, c = (idx & 15) * 4;
            float4 v = *reinterpret_cast<const float4*>(B1 + (size_t)(k0 + r) * INTER + c);
            v.x = __uint_as_float(f2tf32(v.x)); v.y = __uint_as_float(f2tf32(v.y));
            v.z = __uint_as_float(f2tf32(v.z)); v.w = __uint_as_float(f2tf32(v.w));
            *reinterpret_cast<float4*>(&Bs1[r][c]) = v;
            float4 u = *reinterpret_cast<const float4*>(B3 + (size_t)(k0 + r) * INTER + c);
            u.x = __uint_as_float(f2tf32(u.x)); u.y = __uint_as_float(f2tf32(u.y));
            u.z = __uint_as_float(f2tf32(u.z)); u.w = __uint_as_float(f2tf32(u.w));
            *reinterpret_cast<float4*>(&Bs3[r][c]) = u;
        }
        __syncthreads();
#pragma unroll
        for (int ks = 0; ks < BK; ks += 8) {
            uint32_t af[2][4];
#pragma unroll
            for (int mi = 0; mi < 2; mi++) {
                int r = wm + mi * 16 + g;
                af[mi][0] = __float_as_uint(As[r][ks + tg]);
                af[mi][1] = __float_as_uint(As[r + 8][ks + tg]);
                af[mi][2] = __float_as_uint(As[r][ks + tg + 4]);
                af[mi][3] = __float_as_uint(As[r + 8][ks + tg + 4]);
            }
#pragma unroll
            for (int ni = 0; ni < 4; ni++) {
                int c = wn + ni * 8 + g;
                uint32_t b10 = __float_as_uint(Bs1[ks + tg][c]);
                uint32_t b11 = __float_as_uint(Bs1[ks + tg + 4][c]);
                uint32_t b30 = __float_as_uint(Bs3[ks + tg][c]);
                uint32_t b31 = __float_as_uint(Bs3[ks + tg + 4][c]);
#pragma unroll
                for (int mi = 0; mi < 2; mi++) {
                    mma_tf32(acc1[mi][ni], af[mi], b10, b11);
                    mma_tf32(acc3[mi][ni], af[mi], b30, b31);
                }
            }
        }
        __syncthreads();
    }

    // epilogue: bias + silu-glu, write H
#pragma unroll
    for (int mi = 0; mi < 2; mi++) {
#pragma unroll
        for (int ni = 0; ni < 4; ni++) {
            int r0 = m0 + wm + mi * 16 + g;
            int cg = n0 + wn + ni * 8 + tg * 2;
            float b1a = b1[e * INTER + cg], b1b = b1[e * INTER + cg + 1];
            float b3a = b3[e * INTER + cg], b3b = b3[e * INTER + cg + 1];
            float p1, p3;
            p1 = acc1[mi][ni][0] + b1a; p3 = acc3[mi][ni][0] + b3a;
            float h0 = silu_f(p1) * p3;
            p1 = acc1[mi][ni][1] + b1b; p3 = acc3[mi][ni][1] + b3b;
            float h1 = silu_f(p1) * p3;
            *reinterpret_cast<float2*>(&g_H[(size_t)r0 * INTER + cg]) = make_float2(h0, h1);
            p1 = acc1[mi][ni][2] + b1a; p3 = acc3[mi][ni][2] + b3a;
            float h2 = silu_f(p1) * p3;
            p1 = acc1[mi][ni][3] + b1b; p3 = acc3[mi][ni][3] + b3b;
            float h3 = silu_f(p1) * p3;
            *reinterpret_cast<float2*>(&g_H[(size_t)(r0 + 8) * INTER + cg]) = make_float2(h2, h3);
        }
    }
}

// GEMM2: O = H @ W2 + b2   [rows x 1024]
__global__ __launch_bounds__(256) void gemm2_kernel(
    const float* __restrict__ W2, const float* __restrict__ b2) {
    int e = g_tile_e[blockIdx.y];
    if (e < 0) return;
    int m0 = blockIdx.y * BM;
    int n0 = blockIdx.x * BN;

    const float* A = g_H + (size_t)m0 * INTER;
    const float* B = W2 + (size_t)e * INTER * DIM + n0;

    __shared__ float As[BM][BKP];
    __shared__ float Bs[BK][BNP];

    int tid  = threadIdx.x;
    int lane = tid & 31, warp = tid >> 5;
    int wm = (warp >> 1) * 32, wn = (warp & 1) * 32;
    int g  = lane >> 2, tg = lane & 3;

    float acc[2][4][4] = {};

    for (int k0 = 0; k0 < INTER; k0 += BK) {
#pragma unroll
        for (int i = 0; i < 4; i++) {
            int idx = tid + i * 256;
            int r = idx >> 3, c = (idx & 7) * 4;
            float4 v = *reinterpret_cast<const float4*>(A + (size_t)r * INTER + k0 + c);
            v.x = __uint_as_float(f2tf32(v.x)); v.y = __uint_as_float(f2tf32(v.y));
            v.z = __uint_as_float(f2tf32(v.z)); v.w = __uint_as_float(f2tf32(v.w));
            *reinterpret_cast<float4*>(&As[r][c]) = v;
        }
#pragma unroll
        for (int i = 0; i < 2; i++) {
            int idx = tid + i * 256;
            int r = idx >> 4, c = (idx & 15) * 4;
            float4 v = *reinterpret_cast<const float4*>(B + (size_t)(k0 + r) * DIM + c);
            v.x = __uint_as_float(f2tf32(v.x)); v.y = __uint_as_float(f2tf32(v.y));
            v.z = __uint_as_float(f2tf32(v.z)); v.w = __uint_as_float(f2tf32(v.w));
            *reinterpret_cast<float4*>(&Bs[r][c]) = v;
        }
        __syncthreads();
#pragma unroll
        for (int ks = 0; ks < BK; ks += 8) {
            uint32_t af[2][4];
#pragma unroll
            for (int mi = 0; mi < 2; mi++) {
                int r = wm + mi * 16 + g;
                af[mi][0] = __float_as_uint(As[r][ks + tg]);
                af[mi][1] = __float_as_uint(As[r + 8][ks + tg]);
                af[mi][2] = __float_as_uint(As[r][ks + tg + 4]);
                af[mi][3] = __float_as_uint(As[r + 8][ks + tg + 4]);
            }
#pragma unroll
            for (int ni = 0; ni < 4; ni++) {
                int c = wn + ni * 8 + g;
                uint32_t b0 = __float_as_uint(Bs[ks + tg][c]);
                uint32_t b1r = __float_as_uint(Bs[ks + tg + 4][c]);
#pragma unroll
                for (int mi = 0; mi < 2; mi++) mma_tf32(acc[mi][ni], af[mi], b0, b1r);
            }
        }
        __syncthreads();
    }

#pragma unroll
    for (int mi = 0; mi < 2; mi++) {
#pragma unroll
        for (int ni = 0; ni < 4; ni++) {
            int r0 = m0 + wm + mi * 16 + g;
            int cg = n0 + wn + ni * 8 + tg * 2;
            float ba = b2[e * DIM + cg], bb = b2[e * DIM + cg + 1];
            *reinterpret_cast<float2*>(&g_O[(size_t)r0 * DIM + cg]) =
                make_float2(acc[mi][ni][0] + ba, acc[mi][ni][1] + bb);
            *reinterpret_cast<float2*>(&g_O[(size_t)(r0 + 8) * DIM + cg]) =
                make_float2(acc[mi][ni][2] + ba, acc[mi][ni][3] + bb);
        }
    }
}

// ---------------- kernel 6: combine (warp per token) -------------------------
__global__ void combine_kernel(float* __restrict__ y) {
    int t    = (blockIdx.x * blockDim.x + threadIdx.x) >> 5;
    int lane = threadIdx.x & 31;
    if (t >= T_TOK) return;
    int   s0 = g_tok_slot[2 * t],  s1 = g_tok_slot[2 * t + 1];
    float w0 = g_tok_w[2 * t],     w1 = g_tok_w[2 * t + 1];
    const float4* o0 = reinterpret_cast<const float4*>(g_O + (size_t)s0 * DIM);
    const float4* o1 = reinterpret_cast<const float4*>(g_O + (size_t)s1 * DIM);
    float4* yr = reinterpret_cast<float4*>(y + (size_t)t * DIM);
#pragma unroll
    for (int i = 0; i < 8; i++) {
        int c = lane + 32 * i;
        float4 a = o0[c], b = o1[c], r;
        r.x = w0 * a.x + w1 * b.x;
        r.y = w0 * a.y + w1 * b.y;
        r.z = w0 * a.z + w1 * b.z;
        r.w = w0 * a.w + w1 * b.w;
        yr[c] = r;
    }
}

// ---------------- launcher ---------------------------------------------------
extern "C" void kernel_launch(void* const* d_in, const int* in_sizes, int n_in,
                              void* d_out, int out_size) {
    const float* x  = (const float*)d_in[0];
    const float* Wg = (const float*)d_in[1];
    const float* bg = (const float*)d_in[2];
    const float* W1 = (const float*)d_in[3];
    const float* b1 = (const float*)d_in[4];
    const float* W2 = (const float*)d_in[5];
    const float* b2 = (const float*)d_in[6];
    const float* W3 = (const float*)d_in[7];
    const float* b3 = (const float*)d_in[8];
    float* y = (float*)d_out;

    zero_kernel<<<1, 32>>>();
    gate_kernel<<<T_TOK / 8, 256>>>(x, Wg, bg);
    offsets_kernel<<<1, 1>>>();
    assign_gather_kernel<<<NA / 8, 256>>>(x);
    gemm1_kernel<<<dim3(INTER / BN, NT_MAX), 256>>>(W1, b1, W3, b3);
    gemm2_kernel<<<dim3(DIM / BN, NT_MAX), 256>>>(W2, b2);
    combine_kernel<<<T_TOK / 8, 256>>>(y);
}

// round 5
// speedup vs baseline: 1.0898x; 1.0898x over previous
#include <cuda_runtime.h>
#include <cstdint>

// Problem constants
#define T_TOK 8192
#define DIM   1024
#define NEXP  16
#define TOPK  2
#define INTER 2048
#define NA    (T_TOK * TOPK)        // 16384 assignments
#define NAP   18432                 // NA + 16*128 padding capacity
#define NT_MAX 144                  // max 128-row M tiles

// ---------------- static device scratch (no allocations allowed) -------------
__device__ int   g_counts[NEXP];
__device__ int   g_poff[NEXP];
__device__ int   g_cursor[NEXP];
__device__ int   g_tile_e[NT_MAX];
__device__ int   g_tok_e[NA];
__device__ float g_tok_w[NA];
__device__ int   g_tok_slot[NA];
__device__ float g_Xg[(size_t)NAP * DIM];    // gathered tokens (tf32-rounded)
__device__ float g_H [(size_t)NAP * INTER];  // GLU hidden (tf32-rounded)
__device__ float g_O [(size_t)NAP * DIM];    // per-assignment expert output

// ---------------- helpers ----------------------------------------------------
__device__ __forceinline__ uint32_t f2tf32(float f) {
    uint32_t r;
    asm("cvt.rna.tf32.f32 %0, %1;\n" : "=r"(r) : "f"(f));
    return r;
}

__device__ __forceinline__ void mma_tf32(float* d, const uint32_t* a,
                                         uint32_t b0, uint32_t b1) {
    asm volatile(
        "mma.sync.aligned.m16n8k8.row.col.f32.tf32.tf32.f32 "
        "{%0,%1,%2,%3},{%4,%5,%6,%7},{%8,%9},{%0,%1,%2,%3};\n"
        : "+f"(d[0]), "+f"(d[1]), "+f"(d[2]), "+f"(d[3])
        : "r"(a[0]), "r"(a[1]), "r"(a[2]), "r"(a[3]), "r"(b0), "r"(b1));
}

__device__ __forceinline__ void cp_async16(void* smem_dst, const void* gmem_src) {
    uint32_t s = (uint32_t)__cvta_generic_to_shared(smem_dst);
    asm volatile("cp.async.cg.shared.global [%0], [%1], 16;\n"
                 :: "r"(s), "l"(gmem_src));
}
#define CP_COMMIT() asm volatile("cp.async.commit_group;\n" ::: "memory")
#define CP_WAIT1()  asm volatile("cp.async.wait_group 1;\n" ::: "memory")

__device__ __forceinline__ float silu_f(float x) {
    return x / (1.0f + __expf(-x));
}

// ---------------- kernel 0: zero per-launch state ----------------------------
__global__ void zero_kernel() {
    int i = threadIdx.x;
    if (i < NEXP) g_counts[i] = 0;
}

// ---------------- kernel 1: gate (one warp per token) ------------------------
__global__ void gate_kernel(const float* __restrict__ x,
                            const float* __restrict__ Wg,
                            const float* __restrict__ bg) {
    int warp = (blockIdx.x * blockDim.x + threadIdx.x) >> 5;
    int lane = threadIdx.x & 31;
    if (warp >= T_TOK) return;
    const float* xr = x + (size_t)warp * DIM;

    float acc[NEXP];
#pragma unroll
    for (int e = 0; e < NEXP; e++) acc[e] = 0.0f;

    for (int d = lane; d < DIM; d += 32) {
        float xv = __ldg(xr + d);
        const float4* w4 = reinterpret_cast<const float4*>(Wg + (size_t)d * NEXP);
        float4 w0 = w4[0], w1 = w4[1], w2 = w4[2], w3 = w4[3];
        acc[0]  += xv * w0.x; acc[1]  += xv * w0.y; acc[2]  += xv * w0.z; acc[3]  += xv * w0.w;
        acc[4]  += xv * w1.x; acc[5]  += xv * w1.y; acc[6]  += xv * w1.z; acc[7]  += xv * w1.w;
        acc[8]  += xv * w2.x; acc[9]  += xv * w2.y; acc[10] += xv * w2.z; acc[11] += xv * w2.w;
        acc[12] += xv * w3.x; acc[13] += xv * w3.y; acc[14] += xv * w3.z; acc[15] += xv * w3.w;
    }
#pragma unroll
    for (int e = 0; e < NEXP; e++) {
        float v = acc[e];
#pragma unroll
        for (int o = 16; o > 0; o >>= 1) v += __shfl_xor_sync(0xffffffffu, v, o);
        acc[e] = v;
    }
    if (lane == 0) {
        float l1 = -1e30f, l2 = -1e30f;
        int i1 = 0, i2 = 0;
#pragma unroll
        for (int e = 0; e < NEXP; e++) {
            float v = acc[e] + bg[e];
            if (v > l1) { l1 = v; i1 = e; }
        }
#pragma unroll
        for (int e = 0; e < NEXP; e++) {
            float v = acc[e] + bg[e];
            if (e != i1 && v > l2) { l2 = v; i2 = e; }
        }
        float e2 = __expf(l2 - l1);
        float w1v = 1.0f / (1.0f + e2);
        float w2v = e2 * w1v;
        g_tok_e[2 * warp]     = i1;
        g_tok_e[2 * warp + 1] = i2;
        g_tok_w[2 * warp]     = w1v;
        g_tok_w[2 * warp + 1] = w2v;
        atomicAdd(&g_counts[i1], 1);
        atomicAdd(&g_counts[i2], 1);
    }
}

// ---------------- kernel 2: padded offsets + tile->expert map ----------------
__global__ void offsets_kernel() {
    if (threadIdx.x != 0 || blockIdx.x != 0) return;
    int run = 0, idx = 0;
    for (int e = 0; e < NEXP; e++) {
        g_poff[e]   = run;
        g_cursor[e] = 0;
        int c  = g_counts[e];
        int pt = (c + 127) >> 7;
        for (int i = 0; i < pt; i++) g_tile_e[idx++] = e;
        run += pt << 7;
    }
    for (; idx < NT_MAX; idx++) g_tile_e[idx] = -1;
}

// ---------------- kernel 3: assign slots + gather rows (tf32-rounded) --------
__global__ void assign_gather_kernel(const float* __restrict__ x) {
    int aw   = (blockIdx.x * blockDim.x + threadIdx.x) >> 5;
    int lane = threadIdx.x & 31;
    if (aw >= NA) return;
    int t = aw >> 1;

    int slot = 0;
    if (lane == 0) {
        int e   = g_tok_e[aw];
        int pos = atomicAdd(&g_cursor[e], 1);
        slot    = g_poff[e] + pos;
        g_tok_slot[aw] = slot;
    }
    slot = __shfl_sync(0xffffffffu, slot, 0);

    const float4* src = reinterpret_cast<const float4*>(x + (size_t)t * DIM);
    float4*       dst = reinterpret_cast<float4*>(g_Xg + (size_t)slot * DIM);
#pragma unroll
    for (int i = 0; i < 8; i++) {
        float4 v = src[lane + 32 * i];
        v.x = __uint_as_float(f2tf32(v.x)); v.y = __uint_as_float(f2tf32(v.y));
        v.z = __uint_as_float(f2tf32(v.z)); v.w = __uint_as_float(f2tf32(v.w));
        dst[lane + 32 * i] = v;
    }
}

// ---------------- GEMM tiles -------------------------------------------------
#define BM  128
#define BN  64
#define BK  32
#define BKP 36          // A smem row pad (144B, 16B aligned)
#define BNP 72          // B smem row pad (288B, 16B aligned)
#define NSTAGE 3
#define AS_ST (BM * BKP)   // 4608 floats / stage
#define BS_ST (BK * BNP)   // 2304 floats / stage

// GEMM1 fused: H = silu(Xg@W1 + b1) * (Xg@W3 + b3)
__global__ __launch_bounds__(256) void gemm1_kernel(
    const float* __restrict__ W1, const float* __restrict__ b1,
    const float* __restrict__ W3, const float* __restrict__ b3) {
    int e = g_tile_e[blockIdx.y];
    if (e < 0) return;
    int m0 = blockIdx.y * BM;
    int n0 = blockIdx.x * BN;

    const float* A  = g_Xg + (size_t)m0 * DIM;
    const float* B1 = W1 + (size_t)e * DIM * INTER + n0;
    const float* B3 = W3 + (size_t)e * DIM * INTER + n0;

    extern __shared__ float smem[];
    float* As  = smem;                           // [NSTAGE][BM][BKP]
    float* Bs1 = smem + NSTAGE * AS_ST;          // [NSTAGE][BK][BNP]
    float* Bs3 = Bs1 + NSTAGE * BS_ST;

    int tid  = threadIdx.x;
    int lane = tid & 31, warp = tid >> 5;
    int wm = (warp >> 1) * 32, wn = (warp & 1) * 32;
    int g  = lane >> 2, tg = lane & 3;

    // per-thread load coordinates
    int ar = tid >> 3,  ac = (tid & 7) * 4;      // A: 4 chunks, rows ar, ar+32..
    int br = tid >> 4,  bc = (tid & 15) * 4;     // B: 2 chunks, rows br, br+16

    float acc1[2][4][4] = {};
    float acc3[2][4][4] = {};

    const int KT = DIM / BK;   // 32

    // stage loader
    auto load_stage = [&](int k0, int st) {
        float* as = As + st * AS_ST;
#pragma unroll
        for (int i = 0; i < 4; i++) {
            int r = ar + i * 32;
            cp_async16(&as[r * BKP + ac], A + (size_t)r * DIM + k0 + ac);
        }
        float* b1s = Bs1 + st * BS_ST;
        float* b3s = Bs3 + st * BS_ST;
#pragma unroll
        for (int i = 0; i < 2; i++) {
            int r = br + i * 16;
            cp_async16(&b1s[r * BNP + bc], B1 + (size_t)(k0 + r) * INTER + bc);
            cp_async16(&b3s[r * BNP + bc], B3 + (size_t)(k0 + r) * INTER + bc);
        }
    };

    load_stage(0, 0);  CP_COMMIT();
    load_stage(BK, 1); CP_COMMIT();

    for (int kt = 0; kt < KT; kt++) {
        CP_WAIT1();
        __syncthreads();
        int nk = kt + 2;
        if (nk < KT) load_stage(nk * BK, nk % NSTAGE);
        CP_COMMIT();

        int st = kt % NSTAGE;
        const float* as  = As  + st * AS_ST;
        const float* b1s = Bs1 + st * BS_ST;
        const float* b3s = Bs3 + st * BS_ST;
#pragma unroll
        for (int ks = 0; ks < BK; ks += 8) {
            uint32_t af[2][4];
#pragma unroll
            for (int mi = 0; mi < 2; mi++) {
                int r = wm + mi * 16 + g;
                af[mi][0] = __float_as_uint(as[r * BKP + ks + tg]);
                af[mi][1] = __float_as_uint(as[(r + 8) * BKP + ks + tg]);
                af[mi][2] = __float_as_uint(as[r * BKP + ks + tg + 4]);
                af[mi][3] = __float_as_uint(as[(r + 8) * BKP + ks + tg + 4]);
            }
#pragma unroll
            for (int ni = 0; ni < 4; ni++) {
                int c = wn + ni * 8 + g;
                uint32_t b10 = f2tf32(b1s[(ks + tg) * BNP + c]);
                uint32_t b11 = f2tf32(b1s[(ks + tg + 4) * BNP + c]);
                uint32_t b30 = f2tf32(b3s[(ks + tg) * BNP + c]);
                uint32_t b31 = f2tf32(b3s[(ks + tg + 4) * BNP + c]);
#pragma unroll
                for (int mi = 0; mi < 2; mi++) {
                    mma_tf32(acc1[mi][ni], af[mi], b10, b11);
                    mma_tf32(acc3[mi][ni], af[mi], b30, b31);
                }
            }
        }
    }

    // epilogue: bias + silu-glu, write H (tf32-rounded for gemm2)
#pragma unroll
    for (int mi = 0; mi < 2; mi++) {
#pragma unroll
        for (int ni = 0; ni < 4; ni++) {
            int r0 = m0 + wm + mi * 16 + g;
            int cg = n0 + wn + ni * 8 + tg * 2;
            float b1a = __ldg(b1 + e * INTER + cg), b1b = __ldg(b1 + e * INTER + cg + 1);
            float b3a = __ldg(b3 + e * INTER + cg), b3b = __ldg(b3 + e * INTER + cg + 1);
            float h0 = silu_f(acc1[mi][ni][0] + b1a) * (acc3[mi][ni][0] + b3a);
            float h1 = silu_f(acc1[mi][ni][1] + b1b) * (acc3[mi][ni][1] + b3b);
            float h2 = silu_f(acc1[mi][ni][2] + b1a) * (acc3[mi][ni][2] + b3a);
            float h3 = silu_f(acc1[mi][ni][3] + b1b) * (acc3[mi][ni][3] + b3b);
            h0 = __uint_as_float(f2tf32(h0)); h1 = __uint_as_float(f2tf32(h1));
            h2 = __uint_as_float(f2tf32(h2)); h3 = __uint_as_float(f2tf32(h3));
            *reinterpret_cast<float2*>(&g_H[(size_t)r0 * INTER + cg]) = make_float2(h0, h1);
            *reinterpret_cast<float2*>(&g_H[(size_t)(r0 + 8) * INTER + cg]) = make_float2(h2, h3);
        }
    }
}

// GEMM2: O = H @ W2 + b2
__global__ __launch_bounds__(256) void gemm2_kernel(
    const float* __restrict__ W2, const float* __restrict__ b2) {
    int e = g_tile_e[blockIdx.y];
    if (e < 0) return;
    int m0 = blockIdx.y * BM;
    int n0 = blockIdx.x * BN;

    const float* A = g_H + (size_t)m0 * INTER;
    const float* B = W2 + (size_t)e * INTER * DIM + n0;

    extern __shared__ float smem[];
    float* As = smem;                       // [NSTAGE][BM][BKP]
    float* Bs = smem + NSTAGE * AS_ST;      // [NSTAGE][BK][BNP]

    int tid  = threadIdx.x;
    int lane = tid & 31, warp = tid >> 5;
    int wm = (warp >> 1) * 32, wn = (warp & 1) * 32;
    int g  = lane >> 2, tg = lane & 3;

    int ar = tid >> 3,  ac = (tid & 7) * 4;
    int br = tid >> 4,  bc = (tid & 15) * 4;

    float acc[2][4][4] = {};

    const int KT = INTER / BK;   // 64

    auto load_stage = [&](int k0, int st) {
        float* as = As + st * AS_ST;
#pragma unroll
        for (int i = 0; i < 4; i++) {
            int r = ar + i * 32;
            cp_async16(&as[r * BKP + ac], A + (size_t)r * INTER + k0 + ac);
        }
        float* bs = Bs + st * BS_ST;
#pragma unroll
        for (int i = 0; i < 2; i++) {
            int r = br + i * 16;
            cp_async16(&bs[r * BNP + bc], B + (size_t)(k0 + r) * DIM + bc);
        }
    };

    load_stage(0, 0);  CP_COMMIT();
    load_stage(BK, 1); CP_COMMIT();

    for (int kt = 0; kt < KT; kt++) {
        CP_WAIT1();
        __syncthreads();
        int nk = kt + 2;
        if (nk < KT) load_stage(nk * BK, nk % NSTAGE);
        CP_COMMIT();

        int st = kt % NSTAGE;
        const float* as = As + st * AS_ST;
        const float* bs = Bs + st * BS_ST;
#pragma unroll
        for (int ks = 0; ks < BK; ks += 8) {
            uint32_t af[2][4];
#pragma unroll
            for (int mi = 0; mi < 2; mi++) {
                int r = wm + mi * 16 + g;
                af[mi][0] = __float_as_uint(as[r * BKP + ks + tg]);
                af[mi][1] = __float_as_uint(as[(r + 8) * BKP + ks + tg]);
                af[mi][2] = __float_as_uint(as[r * BKP + ks + tg + 4]);
                af[mi][3] = __float_as_uint(as[(r + 8) * BKP + ks + tg + 4]);
            }
#pragma unroll
            for (int ni = 0; ni < 4; ni++) {
                int c = wn + ni * 8 + g;
                uint32_t b0v = f2tf32(bs[(ks + tg) * BNP + c]);
                uint32_t b1v = f2tf32(bs[(ks + tg + 4) * BNP + c]);
#pragma unroll
                for (int mi = 0; mi < 2; mi++) mma_tf32(acc[mi][ni], af[mi], b0v, b1v);
            }
        }
    }

#pragma unroll
    for (int mi = 0; mi < 2; mi++) {
#pragma unroll
        for (int ni = 0; ni < 4; ni++) {
            int r0 = m0 + wm + mi * 16 + g;
            int cg = n0 + wn + ni * 8 + tg * 2;
            float ba = __ldg(b2 + e * DIM + cg), bb = __ldg(b2 + e * DIM + cg + 1);
            *reinterpret_cast<float2*>(&g_O[(size_t)r0 * DIM + cg]) =
                make_float2(acc[mi][ni][0] + ba, acc[mi][ni][1] + bb);
            *reinterpret_cast<float2*>(&g_O[(size_t)(r0 + 8) * DIM + cg]) =
                make_float2(acc[mi][ni][2] + ba, acc[mi][ni][3] + bb);
        }
    }
}

// ---------------- kernel 6: combine (warp per token) -------------------------
__global__ void combine_kernel(float* __restrict__ y) {
    int t    = (blockIdx.x * blockDim.x + threadIdx.x) >> 5;
    int lane = threadIdx.x & 31;
    if (t >= T_TOK) return;
    int   s0 = g_tok_slot[2 * t],  s1 = g_tok_slot[2 * t + 1];
    float w0 = g_tok_w[2 * t],     w1 = g_tok_w[2 * t + 1];
    const float4* o0 = reinterpret_cast<const float4*>(g_O + (size_t)s0 * DIM);
    const float4* o1 = reinterpret_cast<const float4*>(g_O + (size_t)s1 * DIM);
    float4* yr = reinterpret_cast<float4*>(y + (size_t)t * DIM);
#pragma unroll
    for (int i = 0; i < 8; i++) {
        int c = lane + 32 * i;
        float4 a = o0[c], b = o1[c], r;
        r.x = w0 * a.x + w1 * b.x;
        r.y = w0 * a.y + w1 * b.y;
        r.z = w0 * a.z + w1 * b.z;
        r.w = w0 * a.w + w1 * b.w;
        yr[c] = r;
    }
}

// ---------------- launcher ---------------------------------------------------
extern "C" void kernel_launch(void* const* d_in, const int* in_sizes, int n_in,
                              void* d_out, int out_size) {
    const float* x  = (const float*)d_in[0];
    const float* Wg = (const float*)d_in[1];
    const float* bg = (const float*)d_in[2];
    const float* W1 = (const float*)d_in[3];
    const float* b1 = (const float*)d_in[4];
    const float* W2 = (const float*)d_in[5];
    const float* b2 = (const float*)d_in[6];
    const float* W3 = (const float*)d_in[7];
    const float* b3 = (const float*)d_in[8];
    float* y = (float*)d_out;

    const int smem1 = NSTAGE * (AS_ST + 2 * BS_ST) * 4;  // 110592 B
    const int smem2 = NSTAGE * (AS_ST + BS_ST) * 4;      //  82944 B
    cudaFuncSetAttribute(gemm1_kernel, cudaFuncAttributeMaxDynamicSharedMemorySize, smem1);
    cudaFuncSetAttribute(gemm2_kernel, cudaFuncAttributeMaxDynamicSharedMemorySize, smem2);

    zero_kernel<<<1, 32>>>();
    gate_kernel<<<T_TOK / 8, 256>>>(x, Wg, bg);
    offsets_kernel<<<1, 1>>>();
    assign_gather_kernel<<<NA / 8, 256>>>(x);
    gemm1_kernel<<<dim3(INTER / BN, NT_MAX), 256, smem1>>>(W1, b1, W3, b3);
    gemm2_kernel<<<dim3(DIM / BN, NT_MAX), 256, smem2>>>(W2, b2);
    combine_kernel<<<T_TOK / 8, 256>>>(y);
}

// round 7
// speedup vs baseline: 1.6482x; 1.5123x over previous
#include <cuda_runtime.h>
#include <cuda_fp16.h>
#include <cstdint>

// Problem constants
#define T_TOK 8192
#define DIM   1024
#define NEXP  16
#define INTER 2048
#define NA    16384
#define NAP   18432
#define NT_MAX 144

// ---------------- static device scratch --------------------------------------
__device__ int    g_counts[NEXP];
__device__ int    g_poff[NEXP];
__device__ int    g_cursor[NEXP];
__device__ int    g_tile_e[NT_MAX];
__device__ int    g_tok_e[NA];
__device__ float  g_tok_w[NA];
__device__ int    g_tok_slot[NA];
__device__ __half g_Xg[(size_t)NAP * DIM];            // gathered tokens (fp16)
__device__ __half g_H [(size_t)NAP * INTER];          // GLU hidden (fp16)
__device__ float  g_O [(size_t)NAP * DIM];            // expert outputs (fp32)
__device__ __half g_W1h[(size_t)NEXP * INTER * DIM];  // W1^T [e][n][k] fp16
__device__ __half g_W3h[(size_t)NEXP * INTER * DIM];  // W3^T [e][n][k]
__device__ __half g_W2h[(size_t)NEXP * DIM * INTER];  // W2^T [e][n][k]

// ---------------- helpers ----------------------------------------------------
__device__ __forceinline__ float silu_f(float x) { return x / (1.0f + __expf(-x)); }

__device__ __forceinline__ void cp_async16(void* smem_dst, const void* gmem_src) {
    uint32_t s = (uint32_t)__cvta_generic_to_shared(smem_dst);
    asm volatile("cp.async.cg.shared.global [%0], [%1], 16;\n" :: "r"(s), "l"(gmem_src));
}
#define CP_COMMIT() asm volatile("cp.async.commit_group;\n" ::: "memory")
#define CP_WAIT1()  asm volatile("cp.async.wait_group 1;\n" ::: "memory")

// m16n8k16 fp16 mma, fp32 accumulate
__device__ __forceinline__ void mma_f16(float* d, const uint32_t* a,
                                        uint32_t b0, uint32_t b1) {
    asm volatile(
        "mma.sync.aligned.m16n8k16.row.col.f32.f16.f16.f32 "
        "{%0,%1,%2,%3},{%4,%5,%6,%7},{%8,%9},{%0,%1,%2,%3};\n"
        : "+f"(d[0]), "+f"(d[1]), "+f"(d[2]), "+f"(d[3])
        : "r"(a[0]), "r"(a[1]), "r"(a[2]), "r"(a[3]), "r"(b0), "r"(b1));
}

// ---------------- weight convert + transpose ([e][R][C]f32 -> [e][C][R]f16) --
__global__ void convt_kernel(const float* __restrict__ src, int sel, int R, int C) {
    __half* dst = (sel == 0) ? g_W1h : ((sel == 1) ? g_W3h : g_W2h);
    __shared__ float t[32][33];
    size_t base = (size_t)blockIdx.z * R * C;
    src += base; dst += base;
    int tx = threadIdx.x, ty = threadIdx.y;
    int x  = blockIdx.x * 32 + tx;       // col in src
    int y0 = blockIdx.y * 32;            // row base in src
#pragma unroll
    for (int j = 0; j < 4; j++)
        t[ty + 8 * j][tx] = src[(size_t)(y0 + ty + 8 * j) * C + x];
    __syncthreads();
#pragma unroll
    for (int j = 0; j < 4; j++)
        dst[(size_t)(blockIdx.x * 32 + ty + 8 * j) * R + (y0 + tx)] =
            __float2half_rn(t[tx][ty + 8 * j]);
}

// ---------------- kernel 0: zero per-launch state ----------------------------
__global__ void zero_kernel() {
    int i = threadIdx.x;
    if (i < NEXP) g_counts[i] = 0;
}

// ---------------- kernel 1: gate (one warp per token) ------------------------
__global__ void gate_kernel(const float* __restrict__ x,
                            const float* __restrict__ Wg,
                            const float* __restrict__ bg) {
    int warp = (blockIdx.x * blockDim.x + threadIdx.x) >> 5;
    int lane = threadIdx.x & 31;
    if (warp >= T_TOK) return;
    const float* xr = x + (size_t)warp * DIM;

    float acc[NEXP];
#pragma unroll
    for (int e = 0; e < NEXP; e++) acc[e] = 0.0f;

    for (int d = lane; d < DIM; d += 32) {
        float xv = __ldg(xr + d);
        const float4* w4 = reinterpret_cast<const float4*>(Wg + (size_t)d * NEXP);
        float4 w0 = w4[0], w1 = w4[1], w2 = w4[2], w3 = w4[3];
        acc[0]  += xv * w0.x; acc[1]  += xv * w0.y; acc[2]  += xv * w0.z; acc[3]  += xv * w0.w;
        acc[4]  += xv * w1.x; acc[5]  += xv * w1.y; acc[6]  += xv * w1.z; acc[7]  += xv * w1.w;
        acc[8]  += xv * w2.x; acc[9]  += xv * w2.y; acc[10] += xv * w2.z; acc[11] += xv * w2.w;
        acc[12] += xv * w3.x; acc[13] += xv * w3.y; acc[14] += xv * w3.z; acc[15] += xv * w3.w;
    }
#pragma unroll
    for (int e = 0; e < NEXP; e++) {
        float v = acc[e];
#pragma unroll
        for (int o = 16; o > 0; o >>= 1) v += __shfl_xor_sync(0xffffffffu, v, o);
        acc[e] = v;
    }
    if (lane == 0) {
        float l1 = -1e30f, l2 = -1e30f;
        int i1 = 0, i2 = 0;
#pragma unroll
        for (int e = 0; e < NEXP; e++) {
            float v = acc[e] + bg[e];
            if (v > l1) { l1 = v; i1 = e; }
        }
#pragma unroll
        for (int e = 0; e < NEXP; e++) {
            float v = acc[e] + bg[e];
            if (e != i1 && v > l2) { l2 = v; i2 = e; }
        }
        float e2 = __expf(l2 - l1);
        float w1v = 1.0f / (1.0f + e2);
        float w2v = e2 * w1v;
        g_tok_e[2 * warp]     = i1;
        g_tok_e[2 * warp + 1] = i2;
        g_tok_w[2 * warp]     = w1v;
        g_tok_w[2 * warp + 1] = w2v;
        atomicAdd(&g_counts[i1], 1);
        atomicAdd(&g_counts[i2], 1);
    }
}

// ---------------- kernel 2: padded offsets + tile->expert map ----------------
__global__ void offsets_kernel() {
    if (threadIdx.x != 0 || blockIdx.x != 0) return;
    int run = 0, idx = 0;
    for (int e = 0; e < NEXP; e++) {
        g_poff[e]   = run;
        g_cursor[e] = 0;
        int c  = g_counts[e];
        int pt = (c + 127) >> 7;
        for (int i = 0; i < pt; i++) g_tile_e[idx++] = e;
        run += pt << 7;
    }
    for (; idx < NT_MAX; idx++) g_tile_e[idx] = -1;
}

// ---------------- kernel 3: assign slots + gather (f32 -> fp16) --------------
__global__ void assign_gather_kernel(const float* __restrict__ x) {
    int aw   = (blockIdx.x * blockDim.x + threadIdx.x) >> 5;
    int lane = threadIdx.x & 31;
    if (aw >= NA) return;
    int t = aw >> 1;

    int slot = 0;
    if (lane == 0) {
        int e   = g_tok_e[aw];
        int pos = atomicAdd(&g_cursor[e], 1);
        slot    = g_poff[e] + pos;
        g_tok_slot[aw] = slot;
    }
    slot = __shfl_sync(0xffffffffu, slot, 0);

    const float2* src = reinterpret_cast<const float2*>(x + (size_t)t * DIM);
    __half2*      dst = reinterpret_cast<__half2*>(g_Xg + (size_t)slot * DIM);
#pragma unroll
    for (int i = 0; i < 16; i++) {
        int c = lane + 32 * i;
        dst[c] = __float22half2_rn(src[c]);
    }
}

// ---------------- GEMM tiles (fp16) ------------------------------------------
#define BM  128
#define BN  64
#define BK  32
#define BKP 40               // half row pad: 80B stride, conflict-free, 16B-aligned
#define NSTAGE 3
#define AS_ST (BM * BKP)     // 5120 halfs / stage
#define BS_ST (BN * BKP)     // 2560 halfs / stage
#define G1_SMEM (NSTAGE * (AS_ST + 2 * BS_ST) * 2)   // 61440 B
#define G2_SMEM (NSTAGE * (AS_ST + BS_ST) * 2)       // 46080 B

// GEMM1 fused: H = silu(Xg@W1 + b1) * (Xg@W3 + b3)
__global__ __launch_bounds__(256) void gemm1_kernel(
    const float* __restrict__ b1, const float* __restrict__ b3) {
    int e = g_tile_e[blockIdx.y];
    if (e < 0) return;
    int m0 = blockIdx.y * BM;
    int n0 = blockIdx.x * BN;

    const __half* A  = g_Xg  + (size_t)m0 * DIM;
    const __half* B1 = g_W1h + (size_t)e * INTER * DIM + (size_t)n0 * DIM;
    const __half* B3 = g_W3h + (size_t)e * INTER * DIM + (size_t)n0 * DIM;

    extern __shared__ __half sm[];
    __half* As  = sm;                       // [NSTAGE][BM][BKP]
    __half* Bs1 = sm + NSTAGE * AS_ST;      // [NSTAGE][BN][BKP]  (n-major!)
    __half* Bs3 = Bs1 + NSTAGE * BS_ST;

    int tid  = threadIdx.x;
    int lane = tid & 31, warp = tid >> 5;
    int wm = (warp >> 1) * 32, wn = (warp & 1) * 32;
    int g  = lane >> 2, tg = lane & 3;

    float acc1[2][4][4] = {};
    float acc3[2][4][4] = {};

    const int KT = DIM / BK;   // 32

    auto load_stage = [&](int k0, int st) {
        __half* as = As + st * AS_ST;
#pragma unroll
        for (int i = 0; i < 2; i++) {               // A: 128 rows x 32 halfs (4 x 16B)
            int idx = tid + i * 256;
            int r = idx >> 2, ch = idx & 3;
            cp_async16(as + r * BKP + ch * 8, A + (size_t)r * DIM + k0 + ch * 8);
        }
        {                                           // B1/B3: 64 rows x 32 halfs
            int r = tid >> 2, ch = tid & 3;
            cp_async16(Bs1 + st * BS_ST + r * BKP + ch * 8,
                       B1 + (size_t)r * DIM + k0 + ch * 8);
            cp_async16(Bs3 + st * BS_ST + r * BKP + ch * 8,
                       B3 + (size_t)r * DIM + k0 + ch * 8);
        }
    };

    load_stage(0, 0);  CP_COMMIT();
    load_stage(BK, 1); CP_COMMIT();

    for (int kt = 0; kt < KT; kt++) {
        CP_WAIT1();
        __syncthreads();
        int nk = kt + 2;
        if (nk < KT) load_stage(nk * BK, nk % NSTAGE);
        CP_COMMIT();

        int st = kt % NSTAGE;
        const __half* as  = As  + st * AS_ST;
        const __half* b1s = Bs1 + st * BS_ST;
        const __half* b3s = Bs3 + st * BS_ST;
#pragma unroll
        for (int ks = 0; ks < BK; ks += 16) {
            uint32_t af[2][4];
#pragma unroll
            for (int mi = 0; mi < 2; mi++) {
                const __half* ap = as + (wm + mi * 16 + g) * BKP + ks + 2 * tg;
                af[mi][0] = *reinterpret_cast<const uint32_t*>(ap);
                af[mi][1] = *reinterpret_cast<const uint32_t*>(ap + 8 * BKP);
                af[mi][2] = *reinterpret_cast<const uint32_t*>(ap + 8);
                af[mi][3] = *reinterpret_cast<const uint32_t*>(ap + 8 * BKP + 8);
            }
#pragma unroll
            for (int ni = 0; ni < 4; ni++) {
                int c = wn + ni * 8 + g;
                const __half* bp1 = b1s + c * BKP + ks + 2 * tg;
                const __half* bp3 = b3s + c * BKP + ks + 2 * tg;
                uint32_t b10 = *reinterpret_cast<const uint32_t*>(bp1);
                uint32_t b11 = *reinterpret_cast<const uint32_t*>(bp1 + 8);
                uint32_t b30 = *reinterpret_cast<const uint32_t*>(bp3);
                uint32_t b31 = *reinterpret_cast<const uint32_t*>(bp3 + 8);
#pragma unroll
                for (int mi = 0; mi < 2; mi++) {
                    mma_f16(acc1[mi][ni], af[mi], b10, b11);
                    mma_f16(acc3[mi][ni], af[mi], b30, b31);
                }
            }
        }
    }

    // epilogue: bias + silu-glu, write H (fp16)
#pragma unroll
    for (int mi = 0; mi < 2; mi++) {
#pragma unroll
        for (int ni = 0; ni < 4; ni++) {
            int r0 = m0 + wm + mi * 16 + g;
            int cg = n0 + wn + ni * 8 + tg * 2;
            float b1a = __ldg(b1 + e * INTER + cg), b1b = __ldg(b1 + e * INTER + cg + 1);
            float b3a = __ldg(b3 + e * INTER + cg), b3b = __ldg(b3 + e * INTER + cg + 1);
            float h0 = silu_f(acc1[mi][ni][0] + b1a) * (acc3[mi][ni][0] + b3a);
            float h1 = silu_f(acc1[mi][ni][1] + b1b) * (acc3[mi][ni][1] + b3b);
            float h2 = silu_f(acc1[mi][ni][2] + b1a) * (acc3[mi][ni][2] + b3a);
            float h3 = silu_f(acc1[mi][ni][3] + b1b) * (acc3[mi][ni][3] + b3b);
            *reinterpret_cast<__half2*>(&g_H[(size_t)r0 * INTER + cg]) =
                __floats2half2_rn(h0, h1);
            *reinterpret_cast<__half2*>(&g_H[(size_t)(r0 + 8) * INTER + cg]) =
                __floats2half2_rn(h2, h3);
        }
    }
}

// GEMM2: O = H @ W2 + b2
__global__ __launch_bounds__(256) void gemm2_kernel(const float* __restrict__ b2) {
    int e = g_tile_e[blockIdx.y];
    if (e < 0) return;
    int m0 = blockIdx.y * BM;
    int n0 = blockIdx.x * BN;

    const __half* A = g_H   + (size_t)m0 * INTER;
    const __half* B = g_W2h + (size_t)e * DIM * INTER + (size_t)n0 * INTER;

    extern __shared__ __half sm[];
    __half* As = sm;                        // [NSTAGE][BM][BKP]
    __half* Bs = sm + NSTAGE * AS_ST;       // [NSTAGE][BN][BKP]

    int tid  = threadIdx.x;
    int lane = tid & 31, warp = tid >> 5;
    int wm = (warp >> 1) * 32, wn = (warp & 1) * 32;
    int g  = lane >> 2, tg = lane & 3;

    float acc[2][4][4] = {};

    const int KT = INTER / BK;   // 64

    auto load_stage = [&](int k0, int st) {
        __half* as = As + st * AS_ST;
#pragma unroll
        for (int i = 0; i < 2; i++) {
            int idx = tid + i * 256;
            int r = idx >> 2, ch = idx & 3;
            cp_async16(as + r * BKP + ch * 8, A + (size_t)r * INTER + k0 + ch * 8);
        }
        {
            int r = tid >> 2, ch = tid & 3;
            cp_async16(Bs + st * BS_ST + r * BKP + ch * 8,
                       B + (size_t)r * INTER + k0 + ch * 8);
        }
    };

    load_stage(0, 0);  CP_COMMIT();
    load_stage(BK, 1); CP_COMMIT();

    for (int kt = 0; kt < KT; kt++) {
        CP_WAIT1();
        __syncthreads();
        int nk = kt + 2;
        if (nk < KT) load_stage(nk * BK, nk % NSTAGE);
        CP_COMMIT();

        int st = kt % NSTAGE;
        const __half* as = As + st * AS_ST;
        const __half* bs = Bs + st * BS_ST;
#pragma unroll
        for (int ks = 0; ks < BK; ks += 16) {
            uint32_t af[2][4];
#pragma unroll
            for (int mi = 0; mi < 2; mi++) {
                const __half* ap = as + (wm + mi * 16 + g) * BKP + ks + 2 * tg;
                af[mi][0] = *reinterpret_cast<const uint32_t*>(ap);
                af[mi][1] = *reinterpret_cast<const uint32_t*>(ap + 8 * BKP);
                af[mi][2] = *reinterpret_cast<const uint32_t*>(ap + 8);
                af[mi][3] = *reinterpret_cast<const uint32_t*>(ap + 8 * BKP + 8);
            }
#pragma unroll
            for (int ni = 0; ni < 4; ni++) {
                int c = wn + ni * 8 + g;
                const __half* bp = bs + c * BKP + ks + 2 * tg;
                uint32_t b0v = *reinterpret_cast<const uint32_t*>(bp);
                uint32_t b1v = *reinterpret_cast<const uint32_t*>(bp + 8);
#pragma unroll
                for (int mi = 0; mi < 2; mi++) mma_f16(acc[mi][ni], af[mi], b0v, b1v);
            }
        }
    }

#pragma unroll
    for (int mi = 0; mi < 2; mi++) {
#pragma unroll
        for (int ni = 0; ni < 4; ni++) {
            int r0 = m0 + wm + mi * 16 + g;
            int cg = n0 + wn + ni * 8 + tg * 2;
            float ba = __ldg(b2 + e * DIM + cg), bb = __ldg(b2 + e * DIM + cg + 1);
            *reinterpret_cast<float2*>(&g_O[(size_t)r0 * DIM + cg]) =
                make_float2(acc[mi][ni][0] + ba, acc[mi][ni][1] + bb);
            *reinterpret_cast<float2*>(&g_O[(size_t)(r0 + 8) * DIM + cg]) =
                make_float2(acc[mi][ni][2] + ba, acc[mi][ni][3] + bb);
        }
    }
}

// ---------------- kernel: combine (warp per token) ---------------------------
__global__ void combine_kernel(float* __restrict__ y) {
    int t    = (blockIdx.x * blockDim.x + threadIdx.x) >> 5;
    int lane = threadIdx.x & 31;
    if (t >= T_TOK) return;
    int   s0 = g_tok_slot[2 * t],  s1 = g_tok_slot[2 * t + 1];
    float w0 = g_tok_w[2 * t],     w1 = g_tok_w[2 * t + 1];
    const float4* o0 = reinterpret_cast<const float4*>(g_O + (size_t)s0 * DIM);
    const float4* o1 = reinterpret_cast<const float4*>(g_O + (size_t)s1 * DIM);
    float4* yr = reinterpret_cast<float4*>(y + (size_t)t * DIM);
#pragma unroll
    for (int i = 0; i < 8; i++) {
        int c = lane + 32 * i;
        float4 a = o0[c], b = o1[c], r;
        r.x = w0 * a.x + w1 * b.x;
        r.y = w0 * a.y + w1 * b.y;
        r.z = w0 * a.z + w1 * b.z;
        r.w = w0 * a.w + w1 * b.w;
        yr[c] = r;
    }
}

// ---------------- launcher ---------------------------------------------------
extern "C" void kernel_launch(void* const* d_in, const int* in_sizes, int n_in,
                              void* d_out, int out_size) {
    const float* x  = (const float*)d_in[0];
    const float* Wg = (const float*)d_in[1];
    const float* bg = (const float*)d_in[2];
    const float* W1 = (const float*)d_in[3];
    const float* b1 = (const float*)d_in[4];
    const float* W2 = (const float*)d_in[5];
    const float* b2 = (const float*)d_in[6];
    const float* W3 = (const float*)d_in[7];
    const float* b3 = (const float*)d_in[8];
    float* y = (float*)d_out;

    cudaFuncSetAttribute(gemm1_kernel, cudaFuncAttributeMaxDynamicSharedMemorySize, G1_SMEM);
    cudaFuncSetAttribute(gemm2_kernel, cudaFuncAttributeMaxDynamicSharedMemorySize, G2_SMEM);

    // fp16 weight transposes: [e][n][k]
    convt_kernel<<<dim3(INTER / 32, DIM / 32, NEXP), dim3(32, 8)>>>(W1, 0, DIM, INTER);
    convt_kernel<<<dim3(INTER / 32, DIM / 32, NEXP), dim3(32, 8)>>>(W3, 1, DIM, INTER);
    convt_kernel<<<dim3(DIM / 32, INTER / 32, NEXP), dim3(32, 8)>>>(W2, 2, INTER, DIM);

    zero_kernel<<<1, 32>>>();
    gate_kernel<<<T_TOK / 8, 256>>>(x, Wg, bg);
    offsets_kernel<<<1, 1>>>();
    assign_gather_kernel<<<NA / 8, 256>>>(x);
    gemm1_kernel<<<dim3(INTER / BN, NT_MAX), 256, G1_SMEM>>>(b1, b3);
    gemm2_kernel<<<dim3(DIM / BN, NT_MAX), 256, G2_SMEM>>>(b2);
    combine_kernel<<<T_TOK / 8, 256>>>(y);
}